// round 9
// baseline (speedup 1.0000x reference)
#include <cuda_runtime.h>
#include <math.h>

#define N_NODES  100000
#define N_EDGES  1600000
#define NG       64
#define F0       32
#define F1       16
#define F2       8
#define NC       6
#define CAP      128          // ELL capacity; Poisson(16) => P(deg>128) ~ 0
#define GRID_P   1184         // persistent grid
#define NWARPS   (GRID_P * 8)
#define CHUNK    ((N_NODES + NWARPS - 1) / NWARPS)   // 11 contiguous nodes/warp

// ---------------- scratch (device globals) ----------------------------------
__device__ int   g_deg[N_NODES];
__device__ int   g_ell[(size_t)N_NODES * CAP];   // ELL src lists
__device__ float g_h1 [N_NODES * F1];            // relu(mlp1 output)
__device__ float g_pool[NG * F2];
__device__ float g_cnt[NG];

// ---------------- kernels ---------------------------------------------------

__global__ void k_zero() {
    int i = blockIdx.x * blockDim.x + threadIdx.x;
    if (i < N_NODES) g_deg[i] = 0;
    if (i < NG * F2) g_pool[i] = 0.f;
    if (i < NG)      g_cnt[i]  = 0.f;
}

__global__ void k_fill(const int* __restrict__ src, const int* __restrict__ dst) {
    int e = blockIdx.x * blockDim.x + threadIdx.x;
    if (e < N_EDGES) {
        int d = dst[e];
        int p = atomicAdd(&g_deg[d], 1);
        if (p < CAP) g_ell[(size_t)d * CAP + p] = src[e];
    }
}

// ===== fused gather1 + MLP1; contiguous chunks; weight-stationary regs ======
__global__ void __launch_bounds__(256)
k_g1m1(const float* __restrict__ x,
       const float* __restrict__ W1a, const float* __restrict__ b1a,
       const float* __restrict__ W1b, const float* __restrict__ b1b) {
    __shared__ float sh[8][F0];        // h0 per warp-node
    __shared__ float st[8][F1];        // relu(layer1)

    int tid  = threadIdx.x;
    int wid  = tid >> 5;
    int lane = tid & 31;
    int slot = lane >> 3;              // 0..3 edge slot
    int q    = lane & 7;               // row quarter (float4)
    int j    = lane & 15;              // output index
    int half = lane >> 4;              // f-range half

    // weight-stationary: lane j, half h owns Wa[h*16+f][j] and Wb[h*8+k][j]
    float wa[16], wb[8];
#pragma unroll
    for (int f = 0; f < 16; ++f) wa[f] = __ldg(&W1a[(half * 16 + f) * F1 + j]);
#pragma unroll
    for (int k = 0; k < 8;  ++k) wb[k] = __ldg(&W1b[(half * 8  + k) * F1 + j]);
    float ba = __ldg(&b1a[j]);
    float bb = __ldg(&b1b[j]);

    int wg = blockIdx.x * 8 + wid;
    int w0 = wg * CHUNK;
    int w1 = w0 + CHUNK; if (w1 > N_NODES) w1 = N_NODES;
    const float4* xr = (const float4*)x;

    for (int w = w0; w < w1; ++w) {
        int deg = g_deg[w];
        if (deg > CAP) deg = CAP;
        const int* el = g_ell + (size_t)w * CAP;

        float4 a4 = make_float4(0.f, 0.f, 0.f, 0.f);
        int e = 0;
        for (; e + 4 <= deg; e += 4) {
            int s = __ldg(&el[e + slot]);
            float4 v = __ldg(xr + s * 8 + q);
            a4.x += v.x; a4.y += v.y; a4.z += v.z; a4.w += v.w;
        }
        if (slot < deg - e) {
            int s = __ldg(&el[e + slot]);
            float4 v = __ldg(xr + s * 8 + q);
            a4.x += v.x; a4.y += v.y; a4.z += v.z; a4.w += v.w;
        }
#pragma unroll
        for (int off = 16; off >= 8; off >>= 1) {
            a4.x += __shfl_down_sync(0xffffffffu, a4.x, off);
            a4.y += __shfl_down_sync(0xffffffffu, a4.y, off);
            a4.z += __shfl_down_sync(0xffffffffu, a4.z, off);
            a4.w += __shfl_down_sync(0xffffffffu, a4.w, off);
        }
        if (lane < 8) {
            float4 xs = __ldg(xr + w * 8 + q);
            a4.x += xs.x; a4.y += xs.y; a4.z += xs.z; a4.w += xs.w;
            ((float4*)sh[wid])[q] = a4;
        }
        __syncwarp();

        // layer 1: 32->16, halves split the f-range; weights in regs
        float part = 0.f;
#pragma unroll
        for (int f = 0; f < 16; ++f)
            part += sh[wid][half * 16 + f] * wa[f];
        part += __shfl_down_sync(0xffffffffu, part, 16);
        if (lane < F1) st[wid][j] = fmaxf(part + ba, 0.f);
        __syncwarp();

        // layer 2: 16->16, halves split k-range; outer relu fused
        part = 0.f;
#pragma unroll
        for (int k = 0; k < 8; ++k)
            part += st[wid][half * 8 + k] * wb[k];
        part += __shfl_down_sync(0xffffffffu, part, 16);
        if (lane < F1) g_h1[w * F1 + j] = fmaxf(part + bb, 0.f);
        __syncwarp();
    }
}

// ===== fused gather2 + MLP2 + pool; register pooling over sorted batch ======
__global__ void __launch_bounds__(256)
k_g2m2p(const float* __restrict__ W2a, const float* __restrict__ b2a,
        const float* __restrict__ W2b, const float* __restrict__ b2b,
        const int* __restrict__ batch) {
    __shared__ float sh[8][F1];
    __shared__ float st[8][F2];
    __shared__ float sp[NG * F2];
    __shared__ float sc[NG];

    int tid  = threadIdx.x;
    int wid  = tid >> 5;
    int lane = tid & 31;
    int slot = lane >> 2;              // 0..7 edge slot
    int q    = lane & 3;               // row quarter (float4)
    int j8   = lane & 7;
    int h8   = (lane >> 3) & 1;        // f-range half for layer1 (lanes 0..15)

    for (int i = tid; i < NG * F2; i += 256) sp[i] = 0.f;
    for (int i = tid; i < NG;      i += 256) sc[i] = 0.f;

    // weight-stationary
    float wa[8], wb[8];
#pragma unroll
    for (int f = 0; f < 8; ++f) wa[f] = __ldg(&W2a[(h8 * 8 + f) * F2 + j8]);
#pragma unroll
    for (int k = 0; k < 8; ++k) wb[k] = __ldg(&W2b[k * F2 + j8]);
    float ba = __ldg(&b2a[j8]);
    float bb = __ldg(&b2b[j8]);
    __syncthreads();

    int wg = blockIdx.x * 8 + wid;
    int w0 = wg * CHUNK;
    int w1 = w0 + CHUNK; if (w1 > N_NODES) w1 = N_NODES;
    const float4* hr = (const float4*)g_h1;

    float pacc = 0.f;      // lane<8: running pool for cur_b
    float prun = 0.f;      // node count in current segment
    int   cur_b = (w0 < N_NODES) ? __ldg(&batch[w0]) : 0;

    for (int w = w0; w < w1; ++w) {
        int deg = g_deg[w];
        if (deg > CAP) deg = CAP;
        const int* el = g_ell + (size_t)w * CAP;

        float4 a4 = make_float4(0.f, 0.f, 0.f, 0.f);
        int e = 0;
        for (; e + 8 <= deg; e += 8) {
            int s = __ldg(&el[e + slot]);
            float4 v = __ldg(hr + s * 4 + q);
            a4.x += v.x; a4.y += v.y; a4.z += v.z; a4.w += v.w;
        }
        if (slot < deg - e) {
            int s = __ldg(&el[e + slot]);
            float4 v = __ldg(hr + s * 4 + q);
            a4.x += v.x; a4.y += v.y; a4.z += v.z; a4.w += v.w;
        }
#pragma unroll
        for (int off = 16; off >= 4; off >>= 1) {
            a4.x += __shfl_down_sync(0xffffffffu, a4.x, off);
            a4.y += __shfl_down_sync(0xffffffffu, a4.y, off);
            a4.z += __shfl_down_sync(0xffffffffu, a4.z, off);
            a4.w += __shfl_down_sync(0xffffffffu, a4.w, off);
        }
        if (lane < 4) {
            float4 hs = __ldg(hr + w * 4 + q);
            a4.x += hs.x; a4.y += hs.y; a4.z += hs.z; a4.w += hs.w;
            ((float4*)sh[wid])[q] = a4;
        }
        __syncwarp();

        // layer 1: 16->8 on lanes 0..15 (halves split f-range)
        float part = 0.f;
#pragma unroll
        for (int f = 0; f < 8; ++f)
            part += sh[wid][h8 * 8 + f] * wa[f];
        part += __shfl_down_sync(0xffffffffu, part, 8);
        if (lane < F2) st[wid][j8] = fmaxf(part + ba, 0.f);
        __syncwarp();

        // layer 2: 8->8 on lanes 0..7; relu; pool into registers
        int b = __ldg(&batch[w]);
        if (b != cur_b) {
            if (lane < F2 && prun > 0.f) {
                atomicAdd(&sp[cur_b * F2 + lane], pacc);
                if (lane == 0) atomicAdd(&sc[cur_b], prun);
            }
            pacc = 0.f; prun = 0.f; cur_b = b;
        }
        if (lane < F2) {
            float o = bb;
#pragma unroll
            for (int k = 0; k < 8; ++k)
                o += st[wid][k] * wb[k];
            pacc += fmaxf(o, 0.f);
        }
        prun += 1.f;
        __syncwarp();
    }
    if (lane < F2 && prun > 0.f) {
        atomicAdd(&sp[cur_b * F2 + lane], pacc);
        if (lane == 0) atomicAdd(&sc[cur_b], prun);
    }

    __syncthreads();
    for (int i = tid; i < NG * F2; i += 256)
        if (sp[i] != 0.f) atomicAdd(&g_pool[i], sp[i]);
    for (int i = tid; i < NG; i += 256)
        if (sc[i] != 0.f) atomicAdd(&g_cnt[i], sc[i]);
}

__global__ void k_head(const float* __restrict__ Wfc, const float* __restrict__ bfc,
                       float* __restrict__ out) {
    int g = threadIdx.x;
    if (g >= NG) return;
    float c = g_cnt[g];
    c = (c < 1.f) ? 1.f : c;
    float p[F2];
#pragma unroll
    for (int j = 0; j < F2; ++j) p[j] = g_pool[g * F2 + j] / c;
    float l[NC];
#pragma unroll
    for (int j = 0; j < NC; ++j) {
        float a = bfc[j];
#pragma unroll
        for (int f = 0; f < F2; ++f) a += p[f] * Wfc[f * NC + j];
        l[j] = a;
    }
    float m = l[0];
#pragma unroll
    for (int j = 1; j < NC; ++j) m = fmaxf(m, l[j]);
    float s = 0.f;
#pragma unroll
    for (int j = 0; j < NC; ++j) s += expf(l[j] - m);
    float ls = logf(s);
#pragma unroll
    for (int j = 0; j < NC; ++j) out[g * NC + j] = l[j] - m - ls;
}

// ---------------- launch ----------------------------------------------------

extern "C" void kernel_launch(void* const* d_in, const int* in_sizes, int n_in,
                              void* d_out, int out_size) {
    const float* x   = (const float*)d_in[0];
    const int*   ei  = (const int*)d_in[1];     // [2, E] int32
    const int*   bat = (const int*)d_in[2];     // int32
    const float* W1a = (const float*)d_in[3];
    const float* b1a = (const float*)d_in[4];
    const float* W1b = (const float*)d_in[5];
    const float* b1b = (const float*)d_in[6];
    const float* W2a = (const float*)d_in[7];
    const float* b2a = (const float*)d_in[8];
    const float* W2b = (const float*)d_in[9];
    const float* b2b = (const float*)d_in[10];
    const float* Wfc = (const float*)d_in[11];
    const float* bfc = (const float*)d_in[12];
    float* out = (float*)d_out;

    const int* src = ei;
    const int* dst = ei + N_EDGES;

    const int BS = 256;
    int gb_nodes = (N_NODES + BS - 1) / BS;
    int gb_edges = (N_EDGES + BS - 1) / BS;

    k_zero  <<<gb_nodes, BS>>>();
    k_fill  <<<gb_edges, BS>>>(src, dst);
    k_g1m1  <<<GRID_P, BS>>>(x, W1a, b1a, W1b, b1b);
    k_g2m2p <<<GRID_P, BS>>>(W2a, b2a, W2b, b2b, bat);
    k_head  <<<1, 64>>>(Wfc, bfc, out);
}

// round 10
// speedup vs baseline: 1.0176x; 1.0176x over previous
#include <cuda_runtime.h>
#include <math.h>

#define N_NODES  100000
#define N_EDGES  1600000
#define NG       64
#define F0       32
#define F1       16
#define F2       8
#define NC       6
#define CAP      128          // ELL capacity; Poisson(16) => P(deg>128) ~ 0
#define GRID_P   1184         // persistent grid
#define NWARPS   (GRID_P * 8)
#define CHUNK    ((N_NODES + NWARPS - 1) / NWARPS)   // 11 contiguous nodes/warp

// ---------------- scratch (device globals) ----------------------------------
__device__ int   g_deg[N_NODES];
__device__ int   g_ell[(size_t)N_NODES * CAP];   // ELL src lists
__device__ float g_y [N_NODES * F1];             // x @ W1a   (pre-agg transform)
__device__ float g_z [N_NODES * F2];             // h1 @ W2a  (pre-agg transform)
__device__ float g_pool[NG * F2];
__device__ float g_cnt[NG];

// ---------------- kernels ---------------------------------------------------

__global__ void k_zero() {
    int i = blockIdx.x * blockDim.x + threadIdx.x;
    if (i < N_NODES) g_deg[i] = 0;
    if (i < NG * F2) g_pool[i] = 0.f;
    if (i < NG)      g_cnt[i]  = 0.f;
}

__global__ void k_fill(const int* __restrict__ src, const int* __restrict__ dst) {
    int e = blockIdx.x * blockDim.x + threadIdx.x;
    if (e < N_EDGES) {
        int d = dst[e];
        int p = atomicAdd(&g_deg[d], 1);
        if (p < CAP) g_ell[(size_t)d * CAP + p] = src[e];
    }
}

// dense: y[n][j] = sum_f x[n][f] * W1a[f][j]   (no bias; added post-agg)
// thread per output element: n = idx>>4, j = idx&15
__global__ void __launch_bounds__(256)
k_xa(const float* __restrict__ x, const float* __restrict__ W1a) {
    __shared__ float sW[F0 * F1];
    int tid = threadIdx.x;
    for (int i = tid; i < F0 * F1; i += 256) sW[i] = W1a[i];
    __syncthreads();

    int idx = blockIdx.x * 256 + tid;
    if (idx >= N_NODES * F1) return;
    int n = idx >> 4;
    int j = idx & 15;
    const float4* xr = (const float4*)(x + n * F0);
    float acc = 0.f;
#pragma unroll
    for (int f4 = 0; f4 < 8; ++f4) {
        float4 v = __ldg(xr + f4);
        acc += v.x * sW[(f4 * 4 + 0) * F1 + j];
        acc += v.y * sW[(f4 * 4 + 1) * F1 + j];
        acc += v.z * sW[(f4 * 4 + 2) * F1 + j];
        acc += v.w * sW[(f4 * 4 + 3) * F1 + j];
    }
    g_y[idx] = acc;
}

// ===== fused: gather(y) + finish mlp1 + emit z = h1@W2a ======================
// warp per node (contiguous chunk); y rows are 16 floats (4 float4)
__global__ void __launch_bounds__(256, 6)
k_g1m1(const float* __restrict__ b1a,
       const float* __restrict__ W1b, const float* __restrict__ b1b,
       const float* __restrict__ W2a) {
    __shared__ float sh[8][F1];    // pre-activation (y_w + agg)
    __shared__ float st[8][F1];    // relu(layer1)
    __shared__ float su[8][F1];    // h1

    int tid  = threadIdx.x;
    int wid  = tid >> 5;
    int lane = tid & 31;
    int slot = lane >> 2;              // 0..7  edge slot
    int q    = lane & 3;               // 0..3  row quarter (float4)
    int j    = lane & 15;
    int half = lane >> 4;
    int j8   = lane & 7;
    int h8   = (lane >> 3) & 1;

    // weight-stationary registers
    float wb[8], wz[8];
#pragma unroll
    for (int k = 0; k < 8; ++k) wb[k] = __ldg(&W1b[(half * 8 + k) * F1 + j]);
#pragma unroll
    for (int k = 0; k < 8; ++k) wz[k] = __ldg(&W2a[(h8 * 8 + k) * F2 + j8]);
    float ba = __ldg(&b1a[j]);
    float bb = __ldg(&b1b[j]);

    int wg = blockIdx.x * 8 + wid;
    int w0 = wg * CHUNK;
    int w1 = w0 + CHUNK; if (w1 > N_NODES) w1 = N_NODES;
    const float4* yr = (const float4*)g_y;

    for (int w = w0; w < w1; ++w) {
        int deg = g_deg[w];
        if (deg > CAP) deg = CAP;
        const int* el = g_ell + (size_t)w * CAP;

        float4 a4 = make_float4(0.f, 0.f, 0.f, 0.f);
        int e = 0;
        for (; e + 8 <= deg; e += 8) {
            int s = __ldg(&el[e + slot]);
            float4 v = __ldg(yr + s * 4 + q);
            a4.x += v.x; a4.y += v.y; a4.z += v.z; a4.w += v.w;
        }
        if (slot < deg - e) {
            int s = __ldg(&el[e + slot]);
            float4 v = __ldg(yr + s * 4 + q);
            a4.x += v.x; a4.y += v.y; a4.z += v.z; a4.w += v.w;
        }
#pragma unroll
        for (int off = 16; off >= 4; off >>= 1) {
            a4.x += __shfl_down_sync(0xffffffffu, a4.x, off);
            a4.y += __shfl_down_sync(0xffffffffu, a4.y, off);
            a4.z += __shfl_down_sync(0xffffffffu, a4.z, off);
            a4.w += __shfl_down_sync(0xffffffffu, a4.w, off);
        }
        if (lane < 4) {
            float4 ys = __ldg(yr + w * 4 + q);
            a4.x += ys.x; a4.y += ys.y; a4.z += ys.z; a4.w += ys.w;
            ((float4*)sh[wid])[q] = a4;
        }
        __syncwarp();

        // layer-1 activation (matmul already folded into y)
        if (lane < F1) st[wid][j] = fmaxf(sh[wid][j] + ba, 0.f);
        __syncwarp();

        // layer 2: 16->16, halves split k; outer relu fused -> h1
        float part = 0.f;
#pragma unroll
        for (int k = 0; k < 8; ++k)
            part += st[wid][half * 8 + k] * wb[k];
        part += __shfl_down_sync(0xffffffffu, part, 16);
        if (lane < F1) su[wid][j] = fmaxf(part + bb, 0.f);
        __syncwarp();

        // z = h1 @ W2a (no bias, no relu): 16->8 on lanes 0..15
        float pz = 0.f;
#pragma unroll
        for (int k = 0; k < 8; ++k)
            pz += su[wid][h8 * 8 + k] * wz[k];
        pz += __shfl_down_sync(0xffffffffu, pz, 8);
        if (lane < F2) g_z[w * F2 + j8] = pz;
        __syncwarp();
    }
}

// ===== fused: gather(z) + mlp2 activation/layer2 + register pooling =========
// warp per node; z rows are 8 floats (2 float4) -> 16 edges per iteration
__global__ void __launch_bounds__(256, 8)
k_g2m2p(const float* __restrict__ b2a,
        const float* __restrict__ W2b, const float* __restrict__ b2b,
        const int* __restrict__ batch) {
    __shared__ float sh[8][F2];
    __shared__ float st[8][F2];
    __shared__ float sp[NG * F2];
    __shared__ float sc[NG];

    int tid  = threadIdx.x;
    int wid  = tid >> 5;
    int lane = tid & 31;
    int slot = lane >> 1;              // 0..15 edge slot
    int q    = lane & 1;               // 0..1  row half (float4)
    int j8   = lane & 7;

    for (int i = tid; i < NG * F2; i += 256) sp[i] = 0.f;
    for (int i = tid; i < NG;      i += 256) sc[i] = 0.f;

    float wb[8];
#pragma unroll
    for (int k = 0; k < 8; ++k) wb[k] = __ldg(&W2b[k * F2 + j8]);
    float ba = __ldg(&b2a[j8]);
    float bb = __ldg(&b2b[j8]);
    __syncthreads();

    int wg = blockIdx.x * 8 + wid;
    int w0 = wg * CHUNK;
    int w1 = w0 + CHUNK; if (w1 > N_NODES) w1 = N_NODES;
    const float4* zr = (const float4*)g_z;

    float pacc = 0.f, prun = 0.f;
    int   cur_b = (w0 < N_NODES) ? __ldg(&batch[w0]) : 0;

    for (int w = w0; w < w1; ++w) {
        int deg = g_deg[w];
        if (deg > CAP) deg = CAP;
        const int* el = g_ell + (size_t)w * CAP;

        float4 a4 = make_float4(0.f, 0.f, 0.f, 0.f);
        int e = 0;
        for (; e + 16 <= deg; e += 16) {
            int s = __ldg(&el[e + slot]);
            float4 v = __ldg(zr + s * 2 + q);
            a4.x += v.x; a4.y += v.y; a4.z += v.z; a4.w += v.w;
        }
        if (slot < deg - e) {
            int s = __ldg(&el[e + slot]);
            float4 v = __ldg(zr + s * 2 + q);
            a4.x += v.x; a4.y += v.y; a4.z += v.z; a4.w += v.w;
        }
#pragma unroll
        for (int off = 16; off >= 2; off >>= 1) {
            a4.x += __shfl_down_sync(0xffffffffu, a4.x, off);
            a4.y += __shfl_down_sync(0xffffffffu, a4.y, off);
            a4.z += __shfl_down_sync(0xffffffffu, a4.z, off);
            a4.w += __shfl_down_sync(0xffffffffu, a4.w, off);
        }
        if (lane < 2) {
            float4 zs = __ldg(zr + w * 2 + q);
            a4.x += zs.x; a4.y += zs.y; a4.z += zs.z; a4.w += zs.w;
            ((float4*)sh[wid])[q] = a4;
        }
        __syncwarp();

        // layer-1 activation (matmul folded into z)
        if (lane < F2) st[wid][j8] = fmaxf(sh[wid][j8] + ba, 0.f);
        __syncwarp();

        // segment flush on sorted batch
        int b = __ldg(&batch[w]);
        if (b != cur_b) {
            if (lane < F2 && prun > 0.f) {
                atomicAdd(&sp[cur_b * F2 + lane], pacc);
                if (lane == 0) atomicAdd(&sc[cur_b], prun);
            }
            pacc = 0.f; prun = 0.f; cur_b = b;
        }
        // layer 2: 8->8 on lanes 0..7; relu; pool into registers
        if (lane < F2) {
            float o = bb;
#pragma unroll
            for (int k = 0; k < 8; ++k)
                o += st[wid][k] * wb[k];
            pacc += fmaxf(o, 0.f);
        }
        prun += 1.f;
        __syncwarp();
    }
    if (lane < F2 && prun > 0.f) {
        atomicAdd(&sp[cur_b * F2 + lane], pacc);
        if (lane == 0) atomicAdd(&sc[cur_b], prun);
    }

    __syncthreads();
    for (int i = tid; i < NG * F2; i += 256)
        if (sp[i] != 0.f) atomicAdd(&g_pool[i], sp[i]);
    for (int i = tid; i < NG; i += 256)
        if (sc[i] != 0.f) atomicAdd(&g_cnt[i], sc[i]);
}

__global__ void k_head(const float* __restrict__ Wfc, const float* __restrict__ bfc,
                       float* __restrict__ out) {
    int g = threadIdx.x;
    if (g >= NG) return;
    float c = g_cnt[g];
    c = (c < 1.f) ? 1.f : c;
    float p[F2];
#pragma unroll
    for (int j = 0; j < F2; ++j) p[j] = g_pool[g * F2 + j] / c;
    float l[NC];
#pragma unroll
    for (int j = 0; j < NC; ++j) {
        float a = bfc[j];
#pragma unroll
        for (int f = 0; f < F2; ++f) a += p[f] * Wfc[f * NC + j];
        l[j] = a;
    }
    float m = l[0];
#pragma unroll
    for (int j = 1; j < NC; ++j) m = fmaxf(m, l[j]);
    float s = 0.f;
#pragma unroll
    for (int j = 0; j < NC; ++j) s += expf(l[j] - m);
    float ls = logf(s);
#pragma unroll
    for (int j = 0; j < NC; ++j) out[g * NC + j] = l[j] - m - ls;
}

// ---------------- launch ----------------------------------------------------

extern "C" void kernel_launch(void* const* d_in, const int* in_sizes, int n_in,
                              void* d_out, int out_size) {
    const float* x   = (const float*)d_in[0];
    const int*   ei  = (const int*)d_in[1];     // [2, E] int32
    const int*   bat = (const int*)d_in[2];     // int32
    const float* W1a = (const float*)d_in[3];
    const float* b1a = (const float*)d_in[4];
    const float* W1b = (const float*)d_in[5];
    const float* b1b = (const float*)d_in[6];
    const float* W2a = (const float*)d_in[7];
    const float* b2a = (const float*)d_in[8];
    const float* W2b = (const float*)d_in[9];
    const float* b2b = (const float*)d_in[10];
    const float* Wfc = (const float*)d_in[11];
    const float* bfc = (const float*)d_in[12];
    float* out = (float*)d_out;

    const int* src = ei;
    const int* dst = ei + N_EDGES;

    const int BS = 256;
    int gb_nodes = (N_NODES + BS - 1) / BS;
    int gb_edges = (N_EDGES + BS - 1) / BS;
    int gb_y     = (N_NODES * F1 + BS - 1) / BS;

    k_zero  <<<gb_nodes, BS>>>();
    k_fill  <<<gb_edges, BS>>>(src, dst);
    k_xa    <<<gb_y, BS>>>(x, W1a);
    k_g1m1  <<<GRID_P, BS>>>(b1a, W1b, b1b, W2a);
    k_g2m2p <<<GRID_P, BS>>>(b2a, W2b, b2b, bat);
    k_head  <<<1, 64>>>(Wfc, bfc, out);
}

// round 13
// speedup vs baseline: 1.0849x; 1.0662x over previous
#include <cuda_runtime.h>
#include <math.h>

#define N_NODES  100000
#define N_EDGES  1600000
#define NG       64
#define F0       32
#define F1       16
#define F2       8
#define NC       6
#define CAP      128          // ELL capacity; Poisson(16) => P(deg>128) ~ 0
#define GRID_P   1184         // persistent grid = exactly 8 blocks/SM * 148 SMs
#define NWARPS   (GRID_P * 8)
#define CHUNK    ((N_NODES + NWARPS - 1) / NWARPS)   // 11 contiguous nodes/warp

// ---------------- scratch (device globals) ----------------------------------
__device__ int   g_deg[N_NODES];
__device__ int   g_ell[(size_t)N_NODES * CAP];   // ELL src lists
__device__ float g_y [N_NODES * F1];             // x @ W1a   (pre-agg transform)
__device__ float g_z [N_NODES * F2];             // h1 @ W2a  (pre-agg transform)
__device__ float g_pool[NG * F2];
__device__ float g_cnt[NG];

// ---------------- kernels ---------------------------------------------------

__global__ void k_zero() {
    int i = blockIdx.x * blockDim.x + threadIdx.x;
    if (i < N_NODES) g_deg[i] = 0;
    if (i < NG * F2) g_pool[i] = 0.f;
    if (i < NG)      g_cnt[i]  = 0.f;
}

__global__ void k_fill(const int* __restrict__ src, const int* __restrict__ dst) {
    int e = blockIdx.x * blockDim.x + threadIdx.x;
    if (e < N_EDGES) {
        int d = dst[e];
        int p = atomicAdd(&g_deg[d], 1);
        if (p < CAP) g_ell[(size_t)d * CAP + p] = src[e];
    }
}

// dense: y[n][j] = sum_f x[n][f] * W1a[f][j]   (no bias; added post-agg)
__global__ void __launch_bounds__(256)
k_xa(const float* __restrict__ x, const float* __restrict__ W1a) {
    __shared__ float sW[F0 * F1];
    int tid = threadIdx.x;
    for (int i = tid; i < F0 * F1; i += 256) sW[i] = W1a[i];
    __syncthreads();

    int idx = blockIdx.x * 256 + tid;
    if (idx >= N_NODES * F1) return;
    int n = idx >> 4;
    int j = idx & 15;
    const float4* xr = (const float4*)(x + n * F0);
    float acc = 0.f;
#pragma unroll
    for (int f4 = 0; f4 < 8; ++f4) {
        float4 v = __ldg(xr + f4);
        acc += v.x * sW[(f4 * 4 + 0) * F1 + j];
        acc += v.y * sW[(f4 * 4 + 1) * F1 + j];
        acc += v.z * sW[(f4 * 4 + 2) * F1 + j];
        acc += v.w * sW[(f4 * 4 + 3) * F1 + j];
    }
    g_y[idx] = acc;
}

// ===== fused: gather(y) + relu + 16x16 layer + emit z = h1@W2a ==============
// warp per node (contiguous chunk); y rows = 16 floats (4 float4)
// weights in SHARED (keeps regs <= 32 so 8 blocks/SM = one wave)
__global__ void __launch_bounds__(256, 8)
k_g1m1(const float* __restrict__ b1a,
       const float* __restrict__ W1b, const float* __restrict__ b1b,
       const float* __restrict__ W2a) {
    __shared__ float sWb[F1 * 17];     // [k][j] stride 17
    __shared__ float sWz[F1 * 9];      // [k][j8] stride 9
    __shared__ float sba[F1], sbb[F1];
    __shared__ float sh[8][F1];        // pre-activation (agg of y, incl self)
    __shared__ float st[8][F1];        // relu(layer1)
    __shared__ float su[8][F1];        // h1

    int tid  = threadIdx.x;
    int wid  = tid >> 5;
    int lane = tid & 31;
    int slot = lane >> 2;              // 0..7  edge slot
    int q    = lane & 3;               // 0..3  row quarter (float4)
    int j    = lane & 15;
    int half = lane >> 4;
    int j8   = lane & 7;
    int h8   = (lane >> 3) & 1;

    for (int i = tid; i < F1 * F1; i += 256) sWb[(i >> 4) * 17 + (i & 15)] = W1b[i];
    for (int i = tid; i < F1 * F2; i += 256) sWz[(i >> 3) * 9  + (i & 7)]  = W2a[i];
    if (tid < F1) { sba[tid] = b1a[tid]; sbb[tid] = b1b[tid]; }
    __syncthreads();

    int wg = blockIdx.x * 8 + wid;
    int w0 = wg * CHUNK;
    int w1 = w0 + CHUNK; if (w1 > N_NODES) w1 = N_NODES;
    const float4* yr = (const float4*)g_y;

    for (int w = w0; w < w1; ++w) {
        int deg = g_deg[w];
        if (deg > CAP) deg = CAP;
        const int* el = g_ell + (size_t)w * CAP;

        float4 a4 = make_float4(0.f, 0.f, 0.f, 0.f);
        int e = 0;
        for (; e + 8 <= deg; e += 8) {
            int s = __ldg(&el[e + slot]);
            float4 v = __ldg(yr + s * 4 + q);
            a4.x += v.x; a4.y += v.y; a4.z += v.z; a4.w += v.w;
        }
        if (slot < deg - e) {
            int s = __ldg(&el[e + slot]);
            float4 v = __ldg(yr + s * 4 + q);
            a4.x += v.x; a4.y += v.y; a4.z += v.z; a4.w += v.w;
        }
#pragma unroll
        for (int off = 16; off >= 4; off >>= 1) {
            a4.x += __shfl_down_sync(0xffffffffu, a4.x, off);
            a4.y += __shfl_down_sync(0xffffffffu, a4.y, off);
            a4.z += __shfl_down_sync(0xffffffffu, a4.z, off);
            a4.w += __shfl_down_sync(0xffffffffu, a4.w, off);
        }
        if (lane < 4) {
            float4 ys = __ldg(yr + w * 4 + q);
            a4.x += ys.x; a4.y += ys.y; a4.z += ys.z; a4.w += ys.w;
            ((float4*)sh[wid])[q] = a4;
        }
        __syncwarp();

        // layer-1 activation (matmul folded into y)
        if (lane < F1) st[wid][j] = fmaxf(sh[wid][j] + sba[j], 0.f);
        __syncwarp();

        // layer 2: 16->16, halves split k; outer relu fused -> h1
        float part = 0.f;
#pragma unroll
        for (int k = 0; k < 8; ++k)
            part += st[wid][half * 8 + k] * sWb[(half * 8 + k) * 17 + j];
        part += __shfl_down_sync(0xffffffffu, part, 16);
        if (lane < F1) su[wid][j] = fmaxf(part + sbb[j], 0.f);
        __syncwarp();

        // z = h1 @ W2a : 16->8 on lanes 0..15 (halves split k)
        float pz = 0.f;
#pragma unroll
        for (int k = 0; k < 8; ++k)
            pz += su[wid][h8 * 8 + k] * sWz[(h8 * 8 + k) * 9 + j8];
        pz += __shfl_down_sync(0xffffffffu, pz, 8);
        if (lane < F2) g_z[w * F2 + j8] = pz;
        __syncwarp();
    }
}

// ===== fused: gather(z) + relu + 8x8 layer + register pooling ===============
// warp per node; z rows = 8 floats (2 float4) -> 16 edges per iteration
__global__ void __launch_bounds__(256, 8)
k_g2m2p(const float* __restrict__ b2a,
        const float* __restrict__ W2b, const float* __restrict__ b2b,
        const int* __restrict__ batch) {
    __shared__ float sWb[F2 * 9];      // [k][j8] stride 9
    __shared__ float sba[F2], sbb[F2];
    __shared__ float sh[8][F2];
    __shared__ float st[8][F2];
    __shared__ float sp[NG * F2];
    __shared__ float sc[NG];

    int tid  = threadIdx.x;
    int wid  = tid >> 5;
    int lane = tid & 31;
    int slot = lane >> 1;              // 0..15 edge slot
    int q    = lane & 1;               // 0..1  row half (float4)
    int j8   = lane & 7;

    for (int i = tid; i < F2 * F2; i += 256) sWb[(i >> 3) * 9 + (i & 7)] = W2b[i];
    if (tid < F2) { sba[tid] = b2a[tid]; sbb[tid] = b2b[tid]; }
    for (int i = tid; i < NG * F2; i += 256) sp[i] = 0.f;
    for (int i = tid; i < NG;      i += 256) sc[i] = 0.f;
    __syncthreads();

    int wg = blockIdx.x * 8 + wid;
    int w0 = wg * CHUNK;
    int w1 = w0 + CHUNK; if (w1 > N_NODES) w1 = N_NODES;
    const float4* zr = (const float4*)g_z;

    float pacc = 0.f, prun = 0.f;
    int   cur_b = (w0 < N_NODES) ? __ldg(&batch[w0]) : 0;

    for (int w = w0; w < w1; ++w) {
        int deg = g_deg[w];
        if (deg > CAP) deg = CAP;
        const int* el = g_ell + (size_t)w * CAP;

        float4 a4 = make_float4(0.f, 0.f, 0.f, 0.f);
        int e = 0;
        for (; e + 16 <= deg; e += 16) {
            int s = __ldg(&el[e + slot]);
            float4 v = __ldg(zr + s * 2 + q);
            a4.x += v.x; a4.y += v.y; a4.z += v.z; a4.w += v.w;
        }
        if (slot < deg - e) {
            int s = __ldg(&el[e + slot]);
            float4 v = __ldg(zr + s * 2 + q);
            a4.x += v.x; a4.y += v.y; a4.z += v.z; a4.w += v.w;
        }
#pragma unroll
        for (int off = 16; off >= 2; off >>= 1) {
            a4.x += __shfl_down_sync(0xffffffffu, a4.x, off);
            a4.y += __shfl_down_sync(0xffffffffu, a4.y, off);
            a4.z += __shfl_down_sync(0xffffffffu, a4.z, off);
            a4.w += __shfl_down_sync(0xffffffffu, a4.w, off);
        }
        if (lane < 2) {
            float4 zs = __ldg(zr + w * 2 + q);
            a4.x += zs.x; a4.y += zs.y; a4.z += zs.z; a4.w += zs.w;
            ((float4*)sh[wid])[q] = a4;
        }
        __syncwarp();

        // layer-1 activation (matmul folded into z)
        if (lane < F2) st[wid][j8] = fmaxf(sh[wid][j8] + sba[j8], 0.f);
        __syncwarp();

        // segment flush on sorted batch
        int b = __ldg(&batch[w]);
        if (b != cur_b) {
            if (lane < F2 && prun > 0.f) {
                atomicAdd(&sp[cur_b * F2 + lane], pacc);
                if (lane == 0) atomicAdd(&sc[cur_b], prun);
            }
            pacc = 0.f; prun = 0.f; cur_b = b;
        }
        // layer 2: 8->8 on lanes 0..7; relu; pool into registers
        if (lane < F2) {
            float o = sbb[j8];
#pragma unroll
            for (int k = 0; k < 8; ++k)
                o += st[wid][k] * sWb[k * 9 + j8];
            pacc += fmaxf(o, 0.f);
        }
        prun += 1.f;
        __syncwarp();
    }
    if (lane < F2 && prun > 0.f) {
        atomicAdd(&sp[cur_b * F2 + lane], pacc);
        if (lane == 0) atomicAdd(&sc[cur_b], prun);
    }

    __syncthreads();
    for (int i = tid; i < NG * F2; i += 256)
        if (sp[i] != 0.f) atomicAdd(&g_pool[i], sp[i]);
    for (int i = tid; i < NG; i += 256)
        if (sc[i] != 0.f) atomicAdd(&g_cnt[i], sc[i]);
}

__global__ void k_head(const float* __restrict__ Wfc, const float* __restrict__ bfc,
                       float* __restrict__ out) {
    int g = threadIdx.x;
    if (g >= NG) return;
    float c = g_cnt[g];
    c = (c < 1.f) ? 1.f : c;
    float p[F2];
#pragma unroll
    for (int j = 0; j < F2; ++j) p[j] = g_pool[g * F2 + j] / c;
    float l[NC];
#pragma unroll
    for (int j = 0; j < NC; ++j) {
        float a = bfc[j];
#pragma unroll
        for (int f = 0; f < F2; ++f) a += p[f] * Wfc[f * NC + j];
        l[j] = a;
    }
    float m = l[0];
#pragma unroll
    for (int j = 1; j < NC; ++j) m = fmaxf(m, l[j]);
    float s = 0.f;
#pragma unroll
    for (int j = 0; j < NC; ++j) s += expf(l[j] - m);
    float ls = logf(s);
#pragma unroll
    for (int j = 0; j < NC; ++j) out[g * NC + j] = l[j] - m - ls;
}

// ---------------- launch ----------------------------------------------------

extern "C" void kernel_launch(void* const* d_in, const int* in_sizes, int n_in,
                              void* d_out, int out_size) {
    const float* x   = (const float*)d_in[0];
    const int*   ei  = (const int*)d_in[1];     // [2, E] int32
    const int*   bat = (const int*)d_in[2];     // int32
    const float* W1a = (const float*)d_in[3];
    const float* b1a = (const float*)d_in[4];
    const float* W1b = (const float*)d_in[5];
    const float* b1b = (const float*)d_in[6];
    const float* W2a = (const float*)d_in[7];
    const float* b2a = (const float*)d_in[8];
    const float* W2b = (const float*)d_in[9];
    const float* b2b = (const float*)d_in[10];
    const float* Wfc = (const float*)d_in[11];
    const float* bfc = (const float*)d_in[12];
    float* out = (float*)d_out;

    const int* src = ei;
    const int* dst = ei + N_EDGES;

    const int BS = 256;
    int gb_nodes = (N_NODES + BS - 1) / BS;
    int gb_edges = (N_EDGES + BS - 1) / BS;
    int gb_y     = (N_NODES * F1 + BS - 1) / BS;

    k_zero  <<<gb_nodes, BS>>>();
    k_fill  <<<gb_edges, BS>>>(src, dst);
    k_xa    <<<gb_y, BS>>>(x, W1a);
    k_g1m1  <<<GRID_P, BS>>>(b1a, W1b, b1b, W2a);
    k_g2m2p <<<GRID_P, BS>>>(b2a, W2b, b2b, bat);
    k_head  <<<1, 64>>>(Wfc, bfc, out);
}

// round 14
// speedup vs baseline: 1.3044x; 1.2023x over previous
#include <cuda_runtime.h>
#include <math.h>

#define N_NODES  100000
#define N_EDGES  1600000
#define NG       64
#define F0       32
#define F1       16
#define F2       8
#define NC       6
#define CAP      64           // ELL capacity; P(Poisson(16)>64) ~ 1e-20
#define GRID_P   1184         // persistent grid = exactly 8 blocks/SM * 148 SMs
#define NWARPS   (GRID_P * 8)
#define CHUNK    ((N_NODES + NWARPS - 1) / NWARPS)   // 11 contiguous nodes/warp
#define NPAIR    ((CHUNK + 1) / 2)

// ---------------- scratch (device globals) ----------------------------------
__device__ int   g_deg[N_NODES];
__device__ int   g_ell[(size_t)N_NODES * CAP];   // ELL src lists
__device__ float g_y [N_NODES * F1];             // x @ W1a   (pre-agg transform)
__device__ float g_z [N_NODES * F2];             // h1 @ W2a  (pre-agg transform)
__device__ float g_pool[NG * F2];
__device__ float g_cnt[NG];

// ---------------- kernels ---------------------------------------------------

__global__ void k_zero() {
    int i = blockIdx.x * blockDim.x + threadIdx.x;
    if (i < N_NODES) g_deg[i] = 0;
    if (i < NG * F2) g_pool[i] = 0.f;
    if (i < NG)      g_cnt[i]  = 0.f;
}

__global__ void k_fill(const int* __restrict__ src, const int* __restrict__ dst) {
    int e = blockIdx.x * blockDim.x + threadIdx.x;
    if (e < N_EDGES) {
        int d = dst[e];
        int p = atomicAdd(&g_deg[d], 1);
        if (p < CAP) g_ell[(size_t)d * CAP + p] = src[e];
    }
}

// dense: y[n][j] = sum_f x[n][f] * W1a[f][j]   (no bias; added post-agg)
__global__ void __launch_bounds__(256)
k_xa(const float* __restrict__ x, const float* __restrict__ W1a) {
    __shared__ float sW[F0 * F1];
    int tid = threadIdx.x;
    for (int i = tid; i < F0 * F1; i += 256) sW[i] = W1a[i];
    __syncthreads();

    int idx = blockIdx.x * 256 + tid;
    if (idx >= N_NODES * F1) return;
    int n = idx >> 4;
    int j = idx & 15;
    const float4* xr = (const float4*)(x + n * F0);
    float acc = 0.f;
#pragma unroll
    for (int f4 = 0; f4 < 8; ++f4) {
        float4 v = __ldg(xr + f4);
        acc += v.x * sW[(f4 * 4 + 0) * F1 + j];
        acc += v.y * sW[(f4 * 4 + 1) * F1 + j];
        acc += v.z * sW[(f4 * 4 + 2) * F1 + j];
        acc += v.w * sW[(f4 * 4 + 3) * F1 + j];
    }
    g_y[idx] = acc;
}

// ===== fused gather(y)+mlp1+emit z — TWO nodes per warp =====================
// half nh=lane>>4 owns node w0+2p+nh; within half: slot=r>>2 (4 edges/iter), q=r&3
__global__ void __launch_bounds__(256, 8)
k_g1m1(const float* __restrict__ b1a,
       const float* __restrict__ W1b, const float* __restrict__ b1b,
       const float* __restrict__ W2a) {
    __shared__ float sWb[F1 * 17];       // [k][j] stride 17
    __shared__ float sWz[F1 * 9];        // [k][j8] stride 9
    __shared__ float sba[F1], sbb[F1];
    __shared__ float sh[8][2][F1];       // pre-activation per (warp, half)
    __shared__ float st[8][2][F1];       // relu(layer1)
    __shared__ float su[8][2][F1];       // h1

    int tid  = threadIdx.x;
    int wid  = tid >> 5;
    int lane = tid & 31;
    int nh   = lane >> 4;                // node half
    int r    = lane & 15;
    int slot = r >> 2;                   // 0..3 edge slot
    int q    = r & 3;                    // row quarter (float4)
    int j8   = r & 7;
    int kh   = r >> 3;

    for (int i = tid; i < F1 * F1; i += 256) sWb[(i >> 4) * 17 + (i & 15)] = W1b[i];
    for (int i = tid; i < F1 * F2; i += 256) sWz[(i >> 3) * 9  + (i & 7)]  = W2a[i];
    if (tid < F1) { sba[tid] = b1a[tid]; sbb[tid] = b1b[tid]; }
    __syncthreads();

    int wg = blockIdx.x * 8 + wid;
    int w0 = wg * CHUNK;
    int w1 = w0 + CHUNK; if (w1 > N_NODES) w1 = N_NODES;
    const float4* yr = (const float4*)g_y;

    for (int p = 0; p < NPAIR; ++p) {
        int w = w0 + 2 * p + nh;
        bool valid = (w < w1);
        int deg = valid ? g_deg[w] : 0;
        if (deg > CAP) deg = CAP;
        const int* el = g_ell + (size_t)w * CAP;

        float4 a4 = make_float4(0.f, 0.f, 0.f, 0.f);
        int e = 0;
        for (; e + 4 <= deg; e += 4) {
            int s = __ldg(&el[e + slot]);
            float4 v = __ldg(yr + s * 4 + q);
            a4.x += v.x; a4.y += v.y; a4.z += v.z; a4.w += v.w;
        }
        if (slot < deg - e) {
            int s = __ldg(&el[e + slot]);
            float4 v = __ldg(yr + s * 4 + q);
            a4.x += v.x; a4.y += v.y; a4.z += v.z; a4.w += v.w;
        }
        // reduce 4 slots within each 16-lane half (2 levels)
#pragma unroll
        for (int off = 8; off >= 4; off >>= 1) {
            a4.x += __shfl_down_sync(0xffffffffu, a4.x, off);
            a4.y += __shfl_down_sync(0xffffffffu, a4.y, off);
            a4.z += __shfl_down_sync(0xffffffffu, a4.z, off);
            a4.w += __shfl_down_sync(0xffffffffu, a4.w, off);
        }
        if (r < 4 && valid) {
            float4 ys = __ldg(yr + w * 4 + r);
            a4.x += ys.x; a4.y += ys.y; a4.z += ys.z; a4.w += ys.w;
            ((float4*)sh[wid][nh])[r] = a4;
        }
        __syncwarp();

        // layer-1 activation (matmul folded into y); j = r, both halves active
        st[wid][nh][r] = fmaxf(sh[wid][nh][r] + sba[r], 0.f);
        __syncwarp();

        // layer 2: 16->16 full-sum per lane (serves both nodes at once)
        float part = sbb[r];
#pragma unroll
        for (int k = 0; k < 16; ++k)
            part += st[wid][nh][k] * sWb[k * 17 + r];
        su[wid][nh][r] = fmaxf(part, 0.f);
        __syncwarp();

        // z = h1 @ W2a : 16->8 per half, k split across kh
        float pz = 0.f;
#pragma unroll
        for (int k = 0; k < 8; ++k)
            pz += su[wid][nh][kh * 8 + k] * sWz[(kh * 8 + k) * 9 + j8];
        pz += __shfl_down_sync(0xffffffffu, pz, 8);
        if (r < 8 && valid) g_z[w * F2 + j8] = pz;
        __syncwarp();
    }
}

// ===== fused gather(z)+mlp2+pool — TWO nodes per warp =======================
// within half: slot=r>>1 (8 edges/iter), q=r&1
__global__ void __launch_bounds__(256, 8)
k_g2m2p(const float* __restrict__ b2a,
        const float* __restrict__ W2b, const float* __restrict__ b2b,
        const int* __restrict__ batch) {
    __shared__ float sWb[F2 * 9];        // [k][j8] stride 9
    __shared__ float sba[F2], sbb[F2];
    __shared__ float sh[8][2][F2];
    __shared__ float st[8][2][F2];
    __shared__ float sp[NG * F2];
    __shared__ float sc[NG];

    int tid  = threadIdx.x;
    int wid  = tid >> 5;
    int lane = tid & 31;
    int nh   = lane >> 4;
    int r    = lane & 15;
    int slot = r >> 1;                   // 0..7 edge slot
    int q    = r & 1;                    // row half (float4)
    int j8   = r & 7;

    for (int i = tid; i < F2 * F2; i += 256) sWb[(i >> 3) * 9 + (i & 7)] = W2b[i];
    if (tid < F2) { sba[tid] = b2a[tid]; sbb[tid] = b2b[tid]; }
    for (int i = tid; i < NG * F2; i += 256) sp[i] = 0.f;
    for (int i = tid; i < NG;      i += 256) sc[i] = 0.f;
    __syncthreads();

    int wg = blockIdx.x * 8 + wid;
    int w0 = wg * CHUNK;
    int w1 = w0 + CHUNK; if (w1 > N_NODES) w1 = N_NODES;
    const float4* zr = (const float4*)g_z;

    float pacc = 0.f, prun = 0.f;
    int   cur_b = ((w0 + nh) < w1) ? __ldg(&batch[w0 + nh]) : 0;

    for (int p = 0; p < NPAIR; ++p) {
        int w = w0 + 2 * p + nh;
        bool valid = (w < w1);
        int deg = valid ? g_deg[w] : 0;
        if (deg > CAP) deg = CAP;
        const int* el = g_ell + (size_t)w * CAP;

        float4 a4 = make_float4(0.f, 0.f, 0.f, 0.f);
        int e = 0;
        for (; e + 8 <= deg; e += 8) {
            int s = __ldg(&el[e + slot]);
            float4 v = __ldg(zr + s * 2 + q);
            a4.x += v.x; a4.y += v.y; a4.z += v.z; a4.w += v.w;
        }
        if (slot < deg - e) {
            int s = __ldg(&el[e + slot]);
            float4 v = __ldg(zr + s * 2 + q);
            a4.x += v.x; a4.y += v.y; a4.z += v.z; a4.w += v.w;
        }
        // reduce 8 slots within each half (3 levels)
#pragma unroll
        for (int off = 8; off >= 2; off >>= 1) {
            a4.x += __shfl_down_sync(0xffffffffu, a4.x, off);
            a4.y += __shfl_down_sync(0xffffffffu, a4.y, off);
            a4.z += __shfl_down_sync(0xffffffffu, a4.z, off);
            a4.w += __shfl_down_sync(0xffffffffu, a4.w, off);
        }
        if (r < 2 && valid) {
            float4 zs = __ldg(zr + w * 2 + r);
            a4.x += zs.x; a4.y += zs.y; a4.z += zs.z; a4.w += zs.w;
            ((float4*)sh[wid][nh])[r] = a4;
        }
        __syncwarp();

        // activation (matmul folded into z)
        if (r < F2) st[wid][nh][j8] = fmaxf(sh[wid][nh][j8] + sba[j8], 0.f);
        __syncwarp();

        // per-half segment flush on sorted batch
        int b = valid ? __ldg(&batch[w]) : cur_b;
        if (b != cur_b) {
            if (r < F2 && prun > 0.f) {
                atomicAdd(&sp[cur_b * F2 + j8], pacc);
                if (r == 0) atomicAdd(&sc[cur_b], prun);
            }
            pacc = 0.f; prun = 0.f; cur_b = b;
        }
        // layer 2: 8->8 full-sum on 8 lanes per half; relu; register pool
        if (r < F2) {
            float o = sbb[j8];
#pragma unroll
            for (int k = 0; k < 8; ++k)
                o += st[wid][nh][k] * sWb[k * 9 + j8];
            if (valid) pacc += fmaxf(o, 0.f);
        }
        if (valid) prun += 1.f;
        __syncwarp();
    }
    if (r < F2 && prun > 0.f) {
        atomicAdd(&sp[cur_b * F2 + j8], pacc);
        if (r == 0) atomicAdd(&sc[cur_b], prun);
    }

    __syncthreads();
    for (int i = tid; i < NG * F2; i += 256)
        if (sp[i] != 0.f) atomicAdd(&g_pool[i], sp[i]);
    for (int i = tid; i < NG; i += 256)
        if (sc[i] != 0.f) atomicAdd(&g_cnt[i], sc[i]);
}

__global__ void k_head(const float* __restrict__ Wfc, const float* __restrict__ bfc,
                       float* __restrict__ out) {
    int g = threadIdx.x;
    if (g >= NG) return;
    float c = g_cnt[g];
    c = (c < 1.f) ? 1.f : c;
    float p[F2];
#pragma unroll
    for (int j = 0; j < F2; ++j) p[j] = g_pool[g * F2 + j] / c;
    float l[NC];
#pragma unroll
    for (int j = 0; j < NC; ++j) {
        float a = bfc[j];
#pragma unroll
        for (int f = 0; f < F2; ++f) a += p[f] * Wfc[f * NC + j];
        l[j] = a;
    }
    float m = l[0];
#pragma unroll
    for (int j = 1; j < NC; ++j) m = fmaxf(m, l[j]);
    float s = 0.f;
#pragma unroll
    for (int j = 0; j < NC; ++j) s += expf(l[j] - m);
    float ls = logf(s);
#pragma unroll
    for (int j = 0; j < NC; ++j) out[g * NC + j] = l[j] - m - ls;
}

// ---------------- launch ----------------------------------------------------

extern "C" void kernel_launch(void* const* d_in, const int* in_sizes, int n_in,
                              void* d_out, int out_size) {
    const float* x   = (const float*)d_in[0];
    const int*   ei  = (const int*)d_in[1];     // [2, E] int32
    const int*   bat = (const int*)d_in[2];     // int32
    const float* W1a = (const float*)d_in[3];
    const float* b1a = (const float*)d_in[4];
    const float* W1b = (const float*)d_in[5];
    const float* b1b = (const float*)d_in[6];
    const float* W2a = (const float*)d_in[7];
    const float* b2a = (const float*)d_in[8];
    const float* W2b = (const float*)d_in[9];
    const float* b2b = (const float*)d_in[10];
    const float* Wfc = (const float*)d_in[11];
    const float* bfc = (const float*)d_in[12];
    float* out = (float*)d_out;

    const int* src = ei;
    const int* dst = ei + N_EDGES;

    const int BS = 256;
    int gb_nodes = (N_NODES + BS - 1) / BS;
    int gb_edges = (N_EDGES + BS - 1) / BS;
    int gb_y     = (N_NODES * F1 + BS - 1) / BS;

    k_zero  <<<gb_nodes, BS>>>();
    k_fill  <<<gb_edges, BS>>>(src, dst);
    k_xa    <<<gb_y, BS>>>(x, W1a);
    k_g1m1  <<<GRID_P, BS>>>(b1a, W1b, b1b, W2a);
    k_g2m2p <<<GRID_P, BS>>>(b2a, W2b, b2b, bat);
    k_head  <<<1, 64>>>(Wfc, bfc, out);
}